// round 2
// baseline (speedup 1.0000x reference)
#include <cuda_runtime.h>
#include <math.h>

#define B_ 16
#define T_ 512
#define IDIM_ 320
#define CD_ 1024
#define GD_ 4096   // 4*CD
#define HD_ 1024
#define LAYERS_ 4
#define NBLK_ 128  // persistent grid: <= 148 SMs -> all co-resident

typedef unsigned long long ull;

// ---------------- scratch (static device globals; no runtime alloc) ----------------
__device__ float g_xg[(size_t)B_ * T_ * GD_];  // precomputed input gates for current layer
__device__ float g_x [(size_t)B_ * T_ * CD_];  // layer io buffer (ys)
__device__ ull   g_bar;                        // ticket barrier counter (never reset; monotonic)

// ---------------- packed fp32x2 helpers ----------------
__device__ __forceinline__ ull fma2(ull a, ull b, ull c) {
    ull d;
    asm("fma.rn.f32x2 %0, %1, %2, %3;" : "=l"(d) : "l"(a), "l"(b), "l"(c));
    return d;
}
__device__ __forceinline__ ull pack2(float x, float y) {
    ull d;
    asm("mov.b64 %0, {%1, %2};" : "=l"(d) : "f"(x), "f"(y));
    return d;
}
__device__ __forceinline__ float2 unpack2(ull v) {
    float2 r;
    asm("mov.b64 {%0, %1}, %2;" : "=f"(r.x), "=f"(r.y) : "l"(v));
    return r;
}
__device__ __forceinline__ float sigf(float x) { return 1.f / (1.f + expf(-x)); }

// ---------------- persistent LSTM layer kernel ----------------
// 128 blocks x 256 threads. One warp = one cell (4 gate rows x 16 batches, batches
// split into two halves of 8 for register pressure). h_{t-1} staged in smem from
// ys[t-1]. Grid-wide ticket barrier between timesteps. c lives in registers.
__global__ void __launch_bounds__(256) lstm_layer_kernel(
    const float* __restrict__ Whh,   // [4096,1024] this layer
    const float* __restrict__ xg,    // [B*T,4096] precomputed gates (biases folded)
    float* __restrict__ ys)          // [B*T,1024] layer output, also h source
{
    extern __shared__ float hs[];    // [16][1024] = 64KB
    const int tid  = threadIdx.x;
    const int lane = tid & 31;
    const int warp = tid >> 5;
    const int cell = blockIdx.x * 8 + warp;   // 0..1023
    const ull  G   = (ull)gridDim.x;

    const float* w0p = Whh + (size_t)(0 * CD_ + cell) * CD_;
    const float* w1p = Whh + (size_t)(1 * CD_ + cell) * CD_;
    const float* w2p = Whh + (size_t)(2 * CD_ + cell) * CD_;
    const float* w3p = Whh + (size_t)(3 * CD_ + cell) * CD_;

    float creg[2] = {0.f, 0.f};      // cell state for this lane's batch (when lane%4==0)

    for (int t = 0; t < T_; ++t) {
        if (t > 0) {
            // stage h_{t-1} = ys rows (b*T + t-1) into smem
            const float4* src = (const float4*)ys;
#pragma unroll 4
            for (int i = tid; i < B_ * CD_ / 4; i += 256) {
                int b  = i >> 8;          // 256 float4 per batch row
                int k4 = i & 255;
                ((float4*)hs)[i] = src[(size_t)(b * T_ + (t - 1)) * (CD_ / 4) + k4];
            }
            __syncthreads();
        }

#pragma unroll
        for (int bh = 0; bh < 2; ++bh) {
            ull acc[32];              // acc[b*4+g], packed over (k, k+1)
#pragma unroll
            for (int i = 0; i < 32; ++i) acc[i] = 0ULL;

            if (t > 0) {
#pragma unroll 2
                for (int j = 0; j < 8; ++j) {
                    const int k = j * 128 + lane * 4;
                    const ulonglong2 w0 = *(const ulonglong2*)(w0p + k);
                    const ulonglong2 w1 = *(const ulonglong2*)(w1p + k);
                    const ulonglong2 w2 = *(const ulonglong2*)(w2p + k);
                    const ulonglong2 w3 = *(const ulonglong2*)(w3p + k);
#pragma unroll
                    for (int b = 0; b < 8; ++b) {
                        const ulonglong2 h2 = *(const ulonglong2*)(hs + (bh * 8 + b) * CD_ + k);
                        acc[b*4+0] = fma2(w0.x, h2.x, acc[b*4+0]);
                        acc[b*4+0] = fma2(w0.y, h2.y, acc[b*4+0]);
                        acc[b*4+1] = fma2(w1.x, h2.x, acc[b*4+1]);
                        acc[b*4+1] = fma2(w1.y, h2.y, acc[b*4+1]);
                        acc[b*4+2] = fma2(w2.x, h2.x, acc[b*4+2]);
                        acc[b*4+2] = fma2(w2.y, h2.y, acc[b*4+2]);
                        acc[b*4+3] = fma2(w3.x, h2.x, acc[b*4+3]);
                        acc[b*4+3] = fma2(w3.y, h2.y, acc[b*4+3]);
                    }
                }
            }

            // fold packed pairs -> 32 scalars
            float v[32];
#pragma unroll
            for (int i = 0; i < 32; ++i) { float2 p = unpack2(acc[i]); v[i] = p.x + p.y; }

            // multi-value butterfly: lane l ends holding the full sum of value index l
#pragma unroll
            for (int s = 0; s < 5; ++s) {
                const int off = 16 >> s;
                const int n   = 16 >> s;
                const bool hi = (lane & off) != 0;
#pragma unroll
                for (int i = 0; i < n; ++i) {
                    float send = hi ? v[i] : v[i + n];
                    float r = __shfl_xor_sync(0xffffffffu, send, off);
                    v[i] = (hi ? v[i + n] : v[i]) + r;
                }
            }
            // lane 4b+g holds gate g of batch (bh*8+b)
            const float rf = __shfl_xor_sync(0xffffffffu, v[0], 1);
            const float rg = __shfl_xor_sync(0xffffffffu, v[0], 2);
            const float ro = __shfl_xor_sync(0xffffffffu, v[0], 3);

            if ((lane & 3) == 0) {
                const int b = bh * 8 + (lane >> 2);
                const size_t row = (size_t)(b * T_ + t);
                const float* xr = xg + row * GD_ + cell;
                const float gi = v[0] + xr[0];
                const float gf = rf   + xr[CD_];
                const float gg = rg   + xr[2 * CD_];
                const float go = ro   + xr[3 * CD_];
                const float cn = sigf(gf) * creg[bh] + sigf(gi) * tanhf(gg);
                creg[bh] = cn;
                ys[row * CD_ + cell] = sigf(go) * tanhf(cn);
            }
        }

        // ---- grid-wide ticket barrier (monotonic counter, replay-safe) ----
        __threadfence();
        __syncthreads();
        if (tid == 0) {
            ull x = atomicAdd(&g_bar, 1ULL);
            ull target = x - (x % G) + G;
            while (*(volatile ull*)&g_bar < target) { }
        }
        __syncthreads();
    }
}

// ---------------- SGEMM (NT) with packed fp32x2 ----------------
// C[m,n] = sum_k A[m,k]*B[n,k] (+b1[n]+b2[n]); 128x128 tile, BK=8, 256 threads.
// MASK: zero A rows where t >= ilens[b] (m = b*T + t).  TANH: tanh epilogue.
template <int TANH, int MASK>
__global__ void __launch_bounds__(256, 2) sgemm_nt_kernel(
    const float* __restrict__ A, const float* __restrict__ B,
    const float* __restrict__ b1, const float* __restrict__ b2,
    float* __restrict__ C, int M, int N, int K,
    const int* __restrict__ ilens)
{
    __shared__ float As[8][128];
    __shared__ float Bs[8][128];

    const int tid = threadIdx.x;
    const int m0 = blockIdx.y * 128;
    const int n0 = blockIdx.x * 128;

    const int lm = tid >> 1;
    const int lk = (tid & 1) * 4;
    const float* Ap = A + (size_t)(m0 + lm) * K + lk;
    const float* Bp = B + (size_t)(n0 + lm) * K + lk;

    bool amask = true;
    if (MASK) {
        const int m = m0 + lm;
        const int b = m >> 9;          // T = 512
        const int t = m & 511;
        amask = (t < ilens[b]);
    }

    const int tx = tid & 15;
    const int ty = tid >> 4;

    ull acc2[8][4];                    // acc2[i][jp] = packed cols (2jp, 2jp+1)
#pragma unroll
    for (int i = 0; i < 8; ++i)
#pragma unroll
        for (int j = 0; j < 4; ++j) acc2[i][j] = 0ULL;

    for (int k0 = 0; k0 < K; k0 += 8) {
        float4 av = amask ? *(const float4*)(Ap + k0) : make_float4(0.f, 0.f, 0.f, 0.f);
        float4 bv = *(const float4*)(Bp + k0);
        __syncthreads();
        As[lk+0][lm] = av.x; As[lk+1][lm] = av.y; As[lk+2][lm] = av.z; As[lk+3][lm] = av.w;
        Bs[lk+0][lm] = bv.x; Bs[lk+1][lm] = bv.y; Bs[lk+2][lm] = bv.z; Bs[lk+3][lm] = bv.w;
        __syncthreads();
#pragma unroll
        for (int kk = 0; kk < 8; ++kk) {
            float4 a0 = *(const float4*)&As[kk][ty * 8];
            float4 a1 = *(const float4*)&As[kk][ty * 8 + 4];
            ulonglong2 bq0 = *(const ulonglong2*)&Bs[kk][tx * 8];
            ulonglong2 bq1 = *(const ulonglong2*)&Bs[kk][tx * 8 + 4];
            ull b2v[4] = {bq0.x, bq0.y, bq1.x, bq1.y};
            float ar[8] = {a0.x, a0.y, a0.z, a0.w, a1.x, a1.y, a1.z, a1.w};
#pragma unroll
            for (int i = 0; i < 8; ++i) {
                const ull ad = pack2(ar[i], ar[i]);
#pragma unroll
                for (int jp = 0; jp < 4; ++jp)
                    acc2[i][jp] = fma2(ad, b2v[jp], acc2[i][jp]);
            }
        }
    }

    float bvec[8];
#pragma unroll
    for (int j = 0; j < 8; ++j) {
        const int n = n0 + tx * 8 + j;
        float bb = b1 ? b1[n] : 0.f;
        if (b2) bb += b2[n];
        bvec[j] = bb;
    }
#pragma unroll
    for (int i = 0; i < 8; ++i) {
        const size_t m = m0 + ty * 8 + i;
        float* Cp = C + m * N + n0 + tx * 8;
        float o[8];
#pragma unroll
        for (int jp = 0; jp < 4; ++jp) {
            float2 p = unpack2(acc2[i][jp]);
            float v0 = p.x + bvec[2*jp];
            float v1 = p.y + bvec[2*jp+1];
            if (TANH) { v0 = tanhf(v0); v1 = tanhf(v1); }
            o[2*jp] = v0; o[2*jp+1] = v1;
        }
        *(float4*)(Cp)     = make_float4(o[0], o[1], o[2], o[3]);
        *(float4*)(Cp + 4) = make_float4(o[4], o[5], o[6], o[7]);
    }
}

// ---------------- ilens tail ----------------
__global__ void write_tail_kernel(float* __restrict__ out, const int* __restrict__ ilens,
                                  long long base, long long out_size) {
    int i = threadIdx.x;
    if (i < B_ && base + i < out_size) out[base + i] = (float)ilens[i];
}

// ---------------- launch ----------------
extern "C" void kernel_launch(void* const* d_in, const int* in_sizes, int n_in,
                              void* d_out, int out_size)
{
    const float* xpad  = (const float*)d_in[0];   // [B,T,IDIM]
    const float* Wih0  = (const float*)d_in[1];   // [4096,320]
    const float* WihR  = (const float*)d_in[2];   // [3,4096,1024]
    const float* Whh   = (const float*)d_in[3];   // [4,4096,1024]
    const float* bih   = (const float*)d_in[4];   // [4,4096]
    const float* bhh   = (const float*)d_in[5];   // [4,4096]
    const float* Wlast = (const float*)d_in[6];   // [1024,1024]
    const float* blast = (const float*)d_in[7];   // [1024]
    const int*   ilens = (const int*)d_in[8];     // [16]
    float* out = (float*)d_out;

    float *xg, *xb;
    cudaGetSymbolAddress((void**)&xg, g_xg);
    cudaGetSymbolAddress((void**)&xb, g_x);

    cudaFuncSetAttribute(lstm_layer_kernel,
                         cudaFuncAttributeMaxDynamicSharedMemorySize, 65536);

    const int M = B_ * T_;  // 8192

    for (int l = 0; l < LAYERS_; ++l) {
        const float* Ain = (l == 0) ? xpad : xb;
        const float* Bw  = (l == 0) ? Wih0 : (WihR + (size_t)(l - 1) * GD_ * CD_);
        const int K = (l == 0) ? IDIM_ : CD_;

        dim3 grid_xg(GD_ / 128, M / 128);
        sgemm_nt_kernel<0, 0><<<grid_xg, 256>>>(Ain, Bw, bih + l * GD_, bhh + l * GD_,
                                                xg, M, GD_, K, nullptr);

        const float* Wl = Whh + (size_t)l * GD_ * CD_;
        lstm_layer_kernel<<<NBLK_, 256, 65536>>>(Wl, xg, xb);
    }

    dim3 grid_p(HD_ / 128, M / 128);
    sgemm_nt_kernel<1, 1><<<grid_p, 256>>>(xb, Wlast, blast, nullptr,
                                           out, M, HD_, CD_, ilens);

    const long long base = (long long)B_ * T_ * HD_;  // 8388608
    if ((long long)out_size > base)
        write_tail_kernel<<<1, 32>>>(out, ilens, base, (long long)out_size);
}

// round 3
// speedup vs baseline: 1.2141x; 1.2141x over previous
#include <cuda_runtime.h>
#include <math.h>

#define B_ 16
#define T_ 512
#define IDIM_ 320
#define CD_ 1024
#define GD_ 4096   // 4*CD
#define HD_ 1024
#define LAYERS_ 4
#define NBLK_ 128  // persistent grid: <= 148 SMs -> all co-resident

typedef unsigned long long ull;

// ---------------- scratch (static device globals; no runtime alloc) ----------------
__device__ float g_xg[(size_t)B_ * T_ * GD_];  // precomputed input gates for current layer
__device__ float g_x [(size_t)B_ * T_ * CD_];  // layer io buffer (ys)
__device__ float g_hT[CD_ * B_];               // h transposed: hT[cell][b]
__device__ ull   g_bar;                        // ticket barrier counter (monotonic, replay-safe)

// ---------------- packed fp32x2 helpers ----------------
__device__ __forceinline__ ull fma2(ull a, ull b, ull c) {
    ull d;
    asm("fma.rn.f32x2 %0, %1, %2, %3;" : "=l"(d) : "l"(a), "l"(b), "l"(c));
    return d;
}
__device__ __forceinline__ ull add2(ull a, ull b) {
    ull d;
    asm("add.rn.f32x2 %0, %1, %2;" : "=l"(d) : "l"(a), "l"(b));
    return d;
}
__device__ __forceinline__ ull pack2(float x, float y) {
    ull d;
    asm("mov.b64 %0, {%1, %2};" : "=l"(d) : "f"(x), "f"(y));
    return d;
}
__device__ __forceinline__ float2 unpack2(ull v) {
    float2 r;
    asm("mov.b64 {%0, %1}, %2;" : "=f"(r.x), "=f"(r.y) : "l"(v));
    return r;
}
__device__ __forceinline__ float sigf(float x) { return 1.f / (1.f + expf(-x)); }

#define HSTRIDE 20   // padded row stride (floats) for transposed h in smem

// ---------------- persistent LSTM layer kernel ----------------
// 128 blocks x 256 threads, one warp = one cell. h kept transposed (hT[cell][b]) in
// global, staged to smem as hs[k][b] with pad-20 rows (conflict-free LDS.128).
// Accumulators packed over batch pairs: 32 ull = all 16 batches in one pass.
// W rows read via LDG (L1-resident after first step). Grid ticket barrier per step.
__global__ void __launch_bounds__(256) lstm_layer_kernel(
    const float* __restrict__ Whh,   // [4096,1024] this layer
    const float* __restrict__ xg,    // [B*T,4096] precomputed gates (biases folded)
    float* __restrict__ ys,          // [B*T,1024] layer output
    float* __restrict__ hT)          // [1024,16] h transposed
{
    extern __shared__ float hs[];    // [1024][HSTRIDE]
    const int tid  = threadIdx.x;
    const int lane = tid & 31;
    const int warp = tid >> 5;
    const int cell = blockIdx.x * 8 + warp;   // 0..1023
    const ull  G   = (ull)gridDim.x;

    const float* w0p = Whh + (size_t)(0 * CD_ + cell) * CD_;
    const float* w1p = Whh + (size_t)(1 * CD_ + cell) * CD_;
    const float* w2p = Whh + (size_t)(2 * CD_ + cell) * CD_;
    const float* w3p = Whh + (size_t)(3 * CD_ + cell) * CD_;

    float creg = 0.f;                // cell state for batch `lane` (lanes 0..15)

    for (int t = 0; t < T_; ++t) {
        // prefetch xg gate values for this step (DRAM latency hides under fma loop)
        float xgi = 0.f, xgf = 0.f, xgg = 0.f, xgo = 0.f;
        size_t orow = 0;
        if (lane < B_) {
            orow = (size_t)(lane * T_ + t);
            const float* xr = xg + orow * GD_ + cell;
            xgi = __ldg(xr);
            xgf = __ldg(xr + CD_);
            xgg = __ldg(xr + 2 * CD_);
            xgo = __ldg(xr + 3 * CD_);
        }

        ull acc[32];                 // acc[bp*4+g], packed over batches (2bp, 2bp+1)
#pragma unroll
        for (int i = 0; i < 32; ++i) acc[i] = 0ULL;

        if (t > 0) {
            // stage hT[1024][16] -> hs[k][b] (pad HSTRIDE); must bypass L1 (__ldcg):
            // hT addresses repeat every step, written by other SMs.
            const float4* src = (const float4*)hT;
#pragma unroll 4
            for (int i = tid; i < CD_ * B_ / 4; i += 256) {
                float4 v = __ldcg(src + i);
                const int k  = i >> 2;
                const int bq = (i & 3) * 4;
                float* d = hs + k * HSTRIDE + bq;
                d[0] = v.x; d[1] = v.y; d[2] = v.z; d[3] = v.w;
            }
            __syncthreads();

#pragma unroll 1
            for (int j = 0; j < 8; ++j) {
                const int kb = j * 128 + lane;
#pragma unroll
                for (int kc = 0; kc < 4; ++kc) {
                    const int k = kb + kc * 32;
                    const float w0 = __ldg(w0p + k);
                    const float w1 = __ldg(w1p + k);
                    const float w2 = __ldg(w2p + k);
                    const float w3 = __ldg(w3p + k);
                    const ull wp0 = pack2(w0, w0);
                    const ull wp1 = pack2(w1, w1);
                    const ull wp2 = pack2(w2, w2);
                    const ull wp3 = pack2(w3, w3);
                    const float* hrow = hs + k * HSTRIDE;
#pragma unroll
                    for (int bq = 0; bq < 4; ++bq) {
                        const ulonglong2 h2 = *(const ulonglong2*)(hrow + bq * 4);
                        const int i0 = (2 * bq) * 4;
                        const int i1 = (2 * bq + 1) * 4;
                        acc[i0+0] = fma2(wp0, h2.x, acc[i0+0]);
                        acc[i0+1] = fma2(wp1, h2.x, acc[i0+1]);
                        acc[i0+2] = fma2(wp2, h2.x, acc[i0+2]);
                        acc[i0+3] = fma2(wp3, h2.x, acc[i0+3]);
                        acc[i1+0] = fma2(wp0, h2.y, acc[i1+0]);
                        acc[i1+1] = fma2(wp1, h2.y, acc[i1+1]);
                        acc[i1+2] = fma2(wp2, h2.y, acc[i1+2]);
                        acc[i1+3] = fma2(wp3, h2.y, acc[i1+3]);
                    }
                }
            }
        }

        // multi-value butterfly on 32 packed values: lane l ends holding full
        // packed sum of value index l = (bp = l>>2, gate = l&3)
#pragma unroll
        for (int s = 0; s < 5; ++s) {
            const int off = 16 >> s;
            const int n   = 16 >> s;
            const bool hi = (lane & off) != 0;
#pragma unroll
            for (int i = 0; i < n; ++i) {
                ull send = hi ? acc[i] : acc[i + n];
                ull r = __shfl_xor_sync(0xffffffffu, send, off);
                acc[i] = add2(hi ? acc[i + n] : acc[i], r);
            }
        }
        // gather all 4 gates of batch `lane` (lane<16): gate g of bp lives at lane 4bp+g
        const int srcl = (lane >> 1) * 4;
        const ull r0 = __shfl_sync(0xffffffffu, acc[0], srcl + 0);
        const ull r1 = __shfl_sync(0xffffffffu, acc[0], srcl + 1);
        const ull r2 = __shfl_sync(0xffffffffu, acc[0], srcl + 2);
        const ull r3 = __shfl_sync(0xffffffffu, acc[0], srcl + 3);

        if (lane < B_) {
            const bool oddb = (lane & 1) != 0;
            const float2 p0 = unpack2(r0), p1 = unpack2(r1), p2 = unpack2(r2), p3 = unpack2(r3);
            const float gi = (oddb ? p0.y : p0.x) + xgi;
            const float gf = (oddb ? p1.y : p1.x) + xgf;
            const float gg = (oddb ? p2.y : p2.x) + xgg;
            const float go = (oddb ? p3.y : p3.x) + xgo;
            const float cn = sigf(gf) * creg + sigf(gi) * tanhf(gg);
            creg = cn;
            const float hn = sigf(go) * tanhf(cn);
            ys[orow * CD_ + cell] = hn;
            hT[cell * B_ + lane]  = hn;
        }

        // ---- grid-wide ticket barrier (monotonic counter, replay-safe) ----
        __threadfence();
        __syncthreads();
        if (tid == 0) {
            ull x = atomicAdd(&g_bar, 1ULL);
            ull target = x - (x % G) + G;
            while (*(volatile ull*)&g_bar < target) { }
        }
        __syncthreads();
    }
}

// ---------------- SGEMM (NT), double-buffered, packed fp32x2 ----------------
// C[m,n] = sum_k A[m,k]*B[n,k] (+b1[n]+b2[n]); 128x128 tile, BK=16, 256 threads,
// ping-pong smem + register prefetch, one sync per slab.
// Thread tile: rows {ty*4+i, ty*4+64+i}, cols {tx*4+j, tx*4+64+j} -> conflict-free LDS.
// MASK: zero A rows where t >= ilens[b].  TANH: tanh epilogue.
template <int TANH, int MASK>
__global__ void __launch_bounds__(256, 2) sgemm_nt_kernel(
    const float* __restrict__ A, const float* __restrict__ B,
    const float* __restrict__ b1, const float* __restrict__ b2,
    float* __restrict__ C, int M, int N, int K,
    const int* __restrict__ ilens)
{
    __shared__ float As[2][16][132];
    __shared__ float Bs[2][16][132];

    const int tid = threadIdx.x;
    const int m0 = blockIdx.y * 128;
    const int n0 = blockIdx.x * 128;

    const int lm = tid >> 2;          // 0..63
    const int lk = (tid & 3) * 4;     // 0,4,8,12

    const float* Ap0 = A + (size_t)(m0 + lm) * K + lk;
    const float* Ap1 = A + (size_t)(m0 + lm + 64) * K + lk;
    const float* Bp0 = B + (size_t)(n0 + lm) * K + lk;
    const float* Bp1 = B + (size_t)(n0 + lm + 64) * K + lk;

    bool am0 = true, am1 = true;
    if (MASK) {
        int m = m0 + lm;
        am0 = ((m & 511) < ilens[m >> 9]);
        m += 64;
        am1 = ((m & 511) < ilens[m >> 9]);
    }

    const int tx = tid & 15;
    const int ty = tid >> 4;

    ull acc2[8][4];
#pragma unroll
    for (int i = 0; i < 8; ++i)
#pragma unroll
        for (int j = 0; j < 4; ++j) acc2[i][j] = 0ULL;

    const float4 z4 = make_float4(0.f, 0.f, 0.f, 0.f);

    // prologue: tile 0 -> smem[0]
    {
        float4 a0 = am0 ? *(const float4*)(Ap0) : z4;
        float4 a1 = am1 ? *(const float4*)(Ap1) : z4;
        float4 bq0 = *(const float4*)(Bp0);
        float4 bq1 = *(const float4*)(Bp1);
        As[0][lk+0][lm] = a0.x; As[0][lk+1][lm] = a0.y; As[0][lk+2][lm] = a0.z; As[0][lk+3][lm] = a0.w;
        As[0][lk+0][lm+64] = a1.x; As[0][lk+1][lm+64] = a1.y; As[0][lk+2][lm+64] = a1.z; As[0][lk+3][lm+64] = a1.w;
        Bs[0][lk+0][lm] = bq0.x; Bs[0][lk+1][lm] = bq0.y; Bs[0][lk+2][lm] = bq0.z; Bs[0][lk+3][lm] = bq0.w;
        Bs[0][lk+0][lm+64] = bq1.x; Bs[0][lk+1][lm+64] = bq1.y; Bs[0][lk+2][lm+64] = bq1.z; Bs[0][lk+3][lm+64] = bq1.w;
    }
    __syncthreads();

    const int nt = K >> 4;
    int buf = 0;
    for (int tIdx = 0; tIdx < nt; ++tIdx) {
        const bool hasNext = (tIdx + 1) < nt;
        float4 na0, na1, nb0, nb1;
        if (hasNext) {
            const int ko = (tIdx + 1) << 4;
            na0 = am0 ? *(const float4*)(Ap0 + ko) : z4;
            na1 = am1 ? *(const float4*)(Ap1 + ko) : z4;
            nb0 = *(const float4*)(Bp0 + ko);
            nb1 = *(const float4*)(Bp1 + ko);
        }

#pragma unroll
        for (int kk = 0; kk < 16; ++kk) {
            const float4 a0 = *(const float4*)&As[buf][kk][ty * 4];
            const float4 a1 = *(const float4*)&As[buf][kk][ty * 4 + 64];
            const ulonglong2 b0 = *(const ulonglong2*)&Bs[buf][kk][tx * 4];
            const ulonglong2 b1v = *(const ulonglong2*)&Bs[buf][kk][tx * 4 + 64];
            const float ar[8] = {a0.x, a0.y, a0.z, a0.w, a1.x, a1.y, a1.z, a1.w};
#pragma unroll
            for (int i = 0; i < 8; ++i) {
                const ull ad = pack2(ar[i], ar[i]);
                acc2[i][0] = fma2(ad, b0.x,  acc2[i][0]);
                acc2[i][1] = fma2(ad, b0.y,  acc2[i][1]);
                acc2[i][2] = fma2(ad, b1v.x, acc2[i][2]);
                acc2[i][3] = fma2(ad, b1v.y, acc2[i][3]);
            }
        }

        if (hasNext) {
            const int nb = buf ^ 1;
            As[nb][lk+0][lm] = na0.x; As[nb][lk+1][lm] = na0.y; As[nb][lk+2][lm] = na0.z; As[nb][lk+3][lm] = na0.w;
            As[nb][lk+0][lm+64] = na1.x; As[nb][lk+1][lm+64] = na1.y; As[nb][lk+2][lm+64] = na1.z; As[nb][lk+3][lm+64] = na1.w;
            Bs[nb][lk+0][lm] = nb0.x; Bs[nb][lk+1][lm] = nb0.y; Bs[nb][lk+2][lm] = nb0.z; Bs[nb][lk+3][lm] = nb0.w;
            Bs[nb][lk+0][lm+64] = nb1.x; Bs[nb][lk+1][lm+64] = nb1.y; Bs[nb][lk+2][lm+64] = nb1.z; Bs[nb][lk+3][lm+64] = nb1.w;
            __syncthreads();
            buf = nb;
        }
    }

    // bias
    float bv[8];
#pragma unroll
    for (int j = 0; j < 8; ++j) {
        const int n = n0 + ((j < 4) ? (tx * 4 + j) : (64 + tx * 4 + (j - 4)));
        float bb = b1 ? b1[n] : 0.f;
        if (b2) bb += b2[n];
        bv[j] = bb;
    }

#pragma unroll
    for (int i = 0; i < 8; ++i) {
        const int m = m0 + ((i < 4) ? (ty * 4 + i) : (64 + ty * 4 + (i - 4)));
        float o[8];
#pragma unroll
        for (int jp = 0; jp < 4; ++jp) {
            const float2 p = unpack2(acc2[i][jp]);
            const int j0 = 2 * jp;
            float v0 = p.x + bv[j0];
            float v1 = p.y + bv[j0 + 1];
            if (TANH) { v0 = tanhf(v0); v1 = tanhf(v1); }
            o[j0] = v0; o[j0 + 1] = v1;
        }
        float* Cp = C + (size_t)m * N + n0;
        *(float4*)(Cp + tx * 4)      = make_float4(o[0], o[1], o[2], o[3]);
        *(float4*)(Cp + 64 + tx * 4) = make_float4(o[4], o[5], o[6], o[7]);
    }
}

// ---------------- ilens tail ----------------
__global__ void write_tail_kernel(float* __restrict__ out, const int* __restrict__ ilens,
                                  long long base, long long out_size) {
    int i = threadIdx.x;
    if (i < B_ && base + i < out_size) out[base + i] = (float)ilens[i];
}

// ---------------- launch ----------------
extern "C" void kernel_launch(void* const* d_in, const int* in_sizes, int n_in,
                              void* d_out, int out_size)
{
    const float* xpad  = (const float*)d_in[0];   // [B,T,IDIM]
    const float* Wih0  = (const float*)d_in[1];   // [4096,320]
    const float* WihR  = (const float*)d_in[2];   // [3,4096,1024]
    const float* Whh   = (const float*)d_in[3];   // [4,4096,1024]
    const float* bih   = (const float*)d_in[4];   // [4,4096]
    const float* bhh   = (const float*)d_in[5];   // [4,4096]
    const float* Wlast = (const float*)d_in[6];   // [1024,1024]
    const float* blast = (const float*)d_in[7];   // [1024]
    const int*   ilens = (const int*)d_in[8];     // [16]
    float* out = (float*)d_out;

    float *xg, *xb, *hT;
    cudaGetSymbolAddress((void**)&xg, g_xg);
    cudaGetSymbolAddress((void**)&xb, g_x);
    cudaGetSymbolAddress((void**)&hT, g_hT);

    const int smem_step = CD_ * HSTRIDE * 4;  // 81920
    cudaFuncSetAttribute(lstm_layer_kernel,
                         cudaFuncAttributeMaxDynamicSharedMemorySize, smem_step);

    const int M = B_ * T_;  // 8192

    for (int l = 0; l < LAYERS_; ++l) {
        const float* Ain = (l == 0) ? xpad : xb;
        const float* Bw  = (l == 0) ? Wih0 : (WihR + (size_t)(l - 1) * GD_ * CD_);
        const int K = (l == 0) ? IDIM_ : CD_;

        dim3 grid_xg(GD_ / 128, M / 128);
        sgemm_nt_kernel<0, 0><<<grid_xg, 256>>>(Ain, Bw, bih + l * GD_, bhh + l * GD_,
                                                xg, M, GD_, K, nullptr);

        const float* Wl = Whh + (size_t)l * GD_ * CD_;
        lstm_layer_kernel<<<NBLK_, 256, smem_step>>>(Wl, xg, xb, hT);
    }

    dim3 grid_p(HD_ / 128, M / 128);
    sgemm_nt_kernel<1, 1><<<grid_p, 256>>>(xb, Wlast, blast, nullptr,
                                           out, M, HD_, CD_, ilens);

    const long long base = (long long)B_ * T_ * HD_;  // 8388608
    if ((long long)out_size > base)
        write_tail_kernel<<<1, 32>>>(out, ilens, base, (long long)out_size);
}

// round 5
// speedup vs baseline: 1.4617x; 1.2039x over previous
#include <cuda_runtime.h>
#include <cuda_bf16.h>
#include <math.h>

#define B_ 16
#define T_ 512
#define IDIM_ 320
#define CD_ 1024
#define GD_ 4096   // 4*CD
#define HD_ 1024
#define LAYERS_ 4
#define NBLK_ 128  // persistent grid: <= 148 SMs -> all co-resident

typedef unsigned long long ull;
typedef unsigned int uint;

// ---------------- scratch (static device globals; no runtime alloc) ----------------
__device__ float g_xg[(size_t)B_ * T_ * GD_];        // precomputed input gates
__device__ float g_x [(size_t)B_ * T_ * CD_];        // layer io buffer (ys)
__device__ float g_hT[CD_ * B_];                     // h transposed: hT[cell][b]
__device__ ull   g_bar;                              // ticket barrier (monotonic)
__device__ __nv_bfloat16 g_ah[(size_t)B_ * T_ * CD_]; // A hi (bf16 split)
__device__ __nv_bfloat16 g_al[(size_t)B_ * T_ * CD_]; // A lo
__device__ __nv_bfloat16 g_bh[(size_t)GD_ * CD_];     // B hi
__device__ __nv_bfloat16 g_bl[(size_t)GD_ * CD_];     // B lo

// ---------------- packed fp32x2 helpers (step kernel) ----------------
__device__ __forceinline__ ull fma2(ull a, ull b, ull c) {
    ull d;
    asm("fma.rn.f32x2 %0, %1, %2, %3;" : "=l"(d) : "l"(a), "l"(b), "l"(c));
    return d;
}
__device__ __forceinline__ ull add2(ull a, ull b) {
    ull d;
    asm("add.rn.f32x2 %0, %1, %2;" : "=l"(d) : "l"(a), "l"(b));
    return d;
}
__device__ __forceinline__ ull pack2(float x, float y) {
    ull d;
    asm("mov.b64 %0, {%1, %2};" : "=l"(d) : "f"(x), "f"(y));
    return d;
}
__device__ __forceinline__ float2 unpack2(ull v) {
    float2 r;
    asm("mov.b64 {%0, %1}, %2;" : "=f"(r.x), "=f"(r.y) : "l"(v));
    return r;
}
__device__ __forceinline__ float sigf(float x) { return 1.f / (1.f + expf(-x)); }

#define HSTRIDE 20   // padded row stride (floats) for transposed h in smem

// ---------------- bf16 split conversion ----------------
// hi = bf16(x); lo = bf16(x - hi). Optional mask: zero rows with t >= ilens[b].
__global__ void __launch_bounds__(256) conv_split_kernel(
    const float* __restrict__ x, __nv_bfloat16* __restrict__ hi,
    __nv_bfloat16* __restrict__ lo, int n, int K, const int* __restrict__ ilens)
{
    int i = (blockIdx.x * 256 + threadIdx.x) * 2;
    if (i >= n) return;
    float2 v = *(const float2*)(x + i);
    if (ilens) {
        int m = i / K;
        int t = m & (T_ - 1);
        int b = m >> 9;
        if (t >= ilens[b]) { v.x = 0.f; v.y = 0.f; }
    }
    __nv_bfloat162 h2, l2;
    h2.x = __float2bfloat16_rn(v.x);
    h2.y = __float2bfloat16_rn(v.y);
    l2.x = __float2bfloat16_rn(v.x - __bfloat162float(h2.x));
    l2.y = __float2bfloat16_rn(v.y - __bfloat162float(h2.y));
    *(__nv_bfloat162*)(hi + i) = h2;
    *(__nv_bfloat162*)(lo + i) = l2;
}

// ---------------- MMA helpers ----------------
__device__ __forceinline__ void ldmx4(uint& r0, uint& r1, uint& r2, uint& r3,
                                      const __nv_bfloat16* p) {
    uint a = (uint)__cvta_generic_to_shared(p);
    asm volatile("ldmatrix.sync.aligned.m8n8.x4.shared.b16 {%0,%1,%2,%3}, [%4];"
                 : "=r"(r0), "=r"(r1), "=r"(r2), "=r"(r3) : "r"(a));
}
__device__ __forceinline__ void mma16816(float* d, const uint* a, uint b0, uint b1) {
    asm volatile(
        "mma.sync.aligned.m16n8k16.row.col.f32.bf16.bf16.f32 "
        "{%0,%1,%2,%3}, {%4,%5,%6,%7}, {%8,%9}, {%0,%1,%2,%3};"
        : "+f"(d[0]), "+f"(d[1]), "+f"(d[2]), "+f"(d[3])
        : "r"(a[0]), "r"(a[1]), "r"(a[2]), "r"(a[3]), "r"(b0), "r"(b1));
}

// ---------------- bf16x3 GEMM (NT): C = A*B^T + bias, fp32 accum ----------------
// Virtual K'' = 3K over segments (Ah,Bh),(Al,Bh),(Ah,Bl). 128x128x32 tiles,
// 256 threads, 8 warps (4 along M x 2 along N; warp tile 32x64), double-buffered.
#define SPAD 40  // bf16 row stride (32 + 8 pad): conflict-free ldmatrix phases
template <int TANH>
__global__ void __launch_bounds__(256) gemm_bf16x3_kernel(
    const __nv_bfloat16* __restrict__ Ah, const __nv_bfloat16* __restrict__ Al,
    const __nv_bfloat16* __restrict__ Bh, const __nv_bfloat16* __restrict__ Bl,
    const float* __restrict__ b1, const float* __restrict__ b2,
    float* __restrict__ C, int M, int N, int K)
{
    __shared__ __align__(16) __nv_bfloat16 As[2][128][SPAD];
    __shared__ __align__(16) __nv_bfloat16 Bs[2][128][SPAD];

    const int tid  = threadIdx.x;
    const int m0   = blockIdx.y * 128;
    const int n0   = blockIdx.x * 128;
    const int srow = tid >> 1;           // staging: row 0..127
    const int scol = (tid & 1) * 16;     // staging: k offset 0 or 16
    const int lane = tid & 31;
    const int warp = tid >> 5;
    const int wm   = warp & 3;           // 4 warps along M (32 rows each)
    const int wn   = warp >> 2;          // 2 warps along N (64 cols each)

    const int perseg = K >> 5;           // slabs per segment
    const int nslab  = 3 * perseg;

    float acc[2][8][4];
#pragma unroll
    for (int i = 0; i < 2; ++i)
#pragma unroll
        for (int j = 0; j < 8; ++j)
#pragma unroll
            for (int q = 0; q < 4; ++q) acc[i][j][q] = 0.f;

    // staging source for slab s
    auto srcA = [&](int s) -> const uint4* {
        int seg = s / perseg, kin = (s - seg * perseg) * 32;
        const __nv_bfloat16* A = (seg == 1) ? Al : Ah;
        return (const uint4*)(A + (size_t)(m0 + srow) * K + kin + scol);
    };
    auto srcB = [&](int s) -> const uint4* {
        int seg = s / perseg, kin = (s - seg * perseg) * 32;
        const __nv_bfloat16* Bp = (seg == 2) ? Bl : Bh;
        return (const uint4*)(Bp + (size_t)(n0 + srow) * K + kin + scol);
    };

    // prologue: slab 0 -> buffer 0
    {
        const uint4* pa = srcA(0);
        const uint4* pb = srcB(0);
        uint4 a0 = pa[0], a1 = pa[1], bq0 = pb[0], bq1 = pb[1];
        *(uint4*)&As[0][srow][scol]     = a0;
        *(uint4*)&As[0][srow][scol + 8] = a1;
        *(uint4*)&Bs[0][srow][scol]     = bq0;
        *(uint4*)&Bs[0][srow][scol + 8] = bq1;
    }
    __syncthreads();

    for (int s = 0; s < nslab; ++s) {
        const int buf = s & 1;
        const bool has = (s + 1) < nslab;
        uint4 na0, na1, nb0, nb1;
        if (has) {
            const uint4* pa = srcA(s + 1);
            const uint4* pb = srcB(s + 1);
            na0 = pa[0]; na1 = pa[1]; nb0 = pb[0]; nb1 = pb[1];
        }

#pragma unroll
        for (int kh = 0; kh < 2; ++kh) {
            const int rq = lane & 15;
            const int cq = kh * 16 + ((lane >> 4) << 3);
            uint af[2][4];
#pragma unroll
            for (int mi = 0; mi < 2; ++mi)
                ldmx4(af[mi][0], af[mi][1], af[mi][2], af[mi][3],
                      &As[buf][wm * 32 + mi * 16 + rq][cq]);
            uint bf4[4][4];
#pragma unroll
            for (int nq = 0; nq < 4; ++nq)
                ldmx4(bf4[nq][0], bf4[nq][1], bf4[nq][2], bf4[nq][3],
                      &Bs[buf][wn * 64 + nq * 16 + rq][cq]);
#pragma unroll
            for (int mi = 0; mi < 2; ++mi)
#pragma unroll
                for (int nq = 0; nq < 4; ++nq) {
                    mma16816(acc[mi][2 * nq],     af[mi], bf4[nq][0], bf4[nq][2]);
                    mma16816(acc[mi][2 * nq + 1], af[mi], bf4[nq][1], bf4[nq][3]);
                }
        }

        if (has) {
            const int nb = buf ^ 1;
            *(uint4*)&As[nb][srow][scol]     = na0;
            *(uint4*)&As[nb][srow][scol + 8] = na1;
            *(uint4*)&Bs[nb][srow][scol]     = nb0;
            *(uint4*)&Bs[nb][srow][scol + 8] = nb1;
            __syncthreads();
        }
    }

    // epilogue: lane l holds c[r + {0,8}][c + {0,1}], r = l>>2, c = 2*(l&3)
    const int r  = lane >> 2;
    const int cq = (lane & 3) * 2;
#pragma unroll
    for (int mi = 0; mi < 2; ++mi) {
#pragma unroll
        for (int nj = 0; nj < 8; ++nj) {
            const int m1 = m0 + wm * 32 + mi * 16 + r;
            const int n1 = n0 + wn * 64 + nj * 8 + cq;
            float bb0 = b1 ? b1[n1] : 0.f;
            float bb1 = b1 ? b1[n1 + 1] : 0.f;
            if (b2) { bb0 += b2[n1]; bb1 += b2[n1 + 1]; }
            float v0 = acc[mi][nj][0] + bb0;
            float v1 = acc[mi][nj][1] + bb1;
            float v2 = acc[mi][nj][2] + bb0;
            float v3 = acc[mi][nj][3] + bb1;
            if (TANH) { v0 = tanhf(v0); v1 = tanhf(v1); v2 = tanhf(v2); v3 = tanhf(v3); }
            *(float2*)(C + (size_t)m1 * N + n1)       = make_float2(v0, v1);
            *(float2*)(C + (size_t)(m1 + 8) * N + n1) = make_float2(v2, v3);
        }
    }
}

// ---------------- persistent LSTM layer kernel (512 threads, k-split warps) ----------------
// 128 blocks x 512 threads. Cell = blk*8 + (warp&7); warps kh=0/1 split k range.
// hT staged to smem [k][b] pad-20. Packed accumulators over batch pairs.
__global__ void __launch_bounds__(512) lstm_layer_kernel(
    const float* __restrict__ Whh,   // [4096,1024]
    const float* __restrict__ xg,    // [B*T,4096]
    float* __restrict__ ys,          // [B*T,1024]
    float* __restrict__ hT)          // [1024,16]
{
    extern __shared__ float hs[];                    // [1024][HSTRIDE]
    ull* comb = (ull*)(hs + CD_ * HSTRIDE);          // [8*32] flat: warp-cell x lane
    const int tid  = threadIdx.x;
    const int lane = tid & 31;
    const int warp = tid >> 5;                       // 0..15
    const int wc   = warp & 7;
    const int kh   = warp >> 3;                      // k half
    const int cell = blockIdx.x * 8 + wc;
    const ull  G   = (ull)gridDim.x;

    const int koff = kh * 512;
    const float* w0p = Whh + (size_t)(0 * CD_ + cell) * CD_ + koff;
    const float* w1p = Whh + (size_t)(1 * CD_ + cell) * CD_ + koff;
    const float* w2p = Whh + (size_t)(2 * CD_ + cell) * CD_ + koff;
    const float* w3p = Whh + (size_t)(3 * CD_ + cell) * CD_ + koff;

    float creg = 0.f;   // cell state for batch `lane` (kh==0, lane<16)

    for (int t = 0; t < T_; ++t) {
        float xgi = 0.f, xgf = 0.f, xgg = 0.f, xgo = 0.f;
        size_t orow = 0;
        if (kh == 0 && lane < B_) {
            orow = (size_t)(lane * T_ + t);
            const float* xr = xg + orow * GD_ + cell;
            xgi = __ldg(xr);
            xgf = __ldg(xr + CD_);
            xgg = __ldg(xr + 2 * CD_);
            xgo = __ldg(xr + 3 * CD_);
        }

        ull acc[32];
#pragma unroll
        for (int i = 0; i < 32; ++i) acc[i] = 0ULL;

        if (t > 0) {
            const float4* src = (const float4*)hT;
#pragma unroll 4
            for (int i = tid; i < CD_ * B_ / 4; i += 512) {
                float4 v = __ldcg(src + i);
                const int k  = i >> 2;
                const int bq = (i & 3) * 4;
                float* d = hs + k * HSTRIDE + bq;
                d[0] = v.x; d[1] = v.y; d[2] = v.z; d[3] = v.w;
            }
            __syncthreads();

#pragma unroll 1
            for (int j = 0; j < 4; ++j) {
                const int kb = j * 128 + lane;
#pragma unroll
                for (int kc = 0; kc < 4; ++kc) {
                    const int kk = kb + kc * 32;
                    const float w0 = __ldg(w0p + kk);
                    const float w1 = __ldg(w1p + kk);
                    const float w2 = __ldg(w2p + kk);
                    const float w3 = __ldg(w3p + kk);
                    const ull wp0 = pack2(w0, w0);
                    const ull wp1 = pack2(w1, w1);
                    const ull wp2 = pack2(w2, w2);
                    const ull wp3 = pack2(w3, w3);
                    const float* hrow = hs + (koff + kk) * HSTRIDE;
#pragma unroll
                    for (int bq = 0; bq < 4; ++bq) {
                        const ulonglong2 h2 = *(const ulonglong2*)(hrow + bq * 4);
                        const int i0 = (2 * bq) * 4;
                        const int i1 = (2 * bq + 1) * 4;
                        acc[i0+0] = fma2(wp0, h2.x, acc[i0+0]);
                        acc[i0+1] = fma2(wp1, h2.x, acc[i0+1]);
                        acc[i0+2] = fma2(wp2, h2.x, acc[i0+2]);
                        acc[i0+3] = fma2(wp3, h2.x, acc[i0+3]);
                        acc[i1+0] = fma2(wp0, h2.y, acc[i1+0]);
                        acc[i1+1] = fma2(wp1, h2.y, acc[i1+1]);
                        acc[i1+2] = fma2(wp2, h2.y, acc[i1+2]);
                        acc[i1+3] = fma2(wp3, h2.y, acc[i1+3]);
                    }
                }
            }
        }

        // butterfly on 32 packed values: lane l ends holding full packed sum of idx l
#pragma unroll
        for (int s = 0; s < 5; ++s) {
            const int off = 16 >> s;
            const int n   = 16 >> s;
            const bool hi = (lane & off) != 0;
#pragma unroll
            for (int i = 0; i < n; ++i) {
                ull send = hi ? acc[i] : acc[i + n];
                ull r = __shfl_xor_sync(0xffffffffu, send, off);
                acc[i] = add2(hi ? acc[i + n] : acc[i], r);
            }
        }

        // combine the two k-halves via smem
        if (kh == 1) comb[wc * 32 + lane] = acc[0];
        __syncthreads();
        ull tot = acc[0];
        if (kh == 0) tot = add2(tot, comb[wc * 32 + lane]);

        // gather gates of batch `lane`: gate g of bp lives at lane 4bp+g
        const int srcl = (lane >> 1) * 4;
        const ull r0 = __shfl_sync(0xffffffffu, tot, srcl + 0);
        const ull r1 = __shfl_sync(0xffffffffu, tot, srcl + 1);
        const ull r2 = __shfl_sync(0xffffffffu, tot, srcl + 2);
        const ull r3 = __shfl_sync(0xffffffffu, tot, srcl + 3);

        if (kh == 0 && lane < B_) {
            const bool oddb = (lane & 1) != 0;
            const float2 p0 = unpack2(r0), p1 = unpack2(r1), p2 = unpack2(r2), p3 = unpack2(r3);
            const float gi = (oddb ? p0.y : p0.x) + xgi;
            const float gf = (oddb ? p1.y : p1.x) + xgf;
            const float gg = (oddb ? p2.y : p2.x) + xgg;
            const float go = (oddb ? p3.y : p3.x) + xgo;
            const float cn = sigf(gf) * creg + sigf(gi) * tanhf(gg);
            creg = cn;
            const float hn = sigf(go) * tanhf(cn);
            ys[orow * CD_ + cell] = hn;
            hT[cell * B_ + lane]  = hn;
        }

        // grid-wide ticket barrier (monotonic, replay-safe)
        __threadfence();
        __syncthreads();
        if (tid == 0) {
            ull x = atomicAdd(&g_bar, 1ULL);
            ull target = x - (x % G) + G;
            while (*(volatile ull*)&g_bar < target) { }
        }
        __syncthreads();
    }
}

// ---------------- ilens tail ----------------
__global__ void write_tail_kernel(float* __restrict__ out, const int* __restrict__ ilens,
                                  long long base, long long out_size) {
    int i = threadIdx.x;
    if (i < B_ && base + i < out_size) out[base + i] = (float)ilens[i];
}

// ---------------- launch ----------------
extern "C" void kernel_launch(void* const* d_in, const int* in_sizes, int n_in,
                              void* d_out, int out_size)
{
    const float* xpad  = (const float*)d_in[0];   // [B,T,IDIM]
    const float* Wih0  = (const float*)d_in[1];   // [4096,320]
    const float* WihR  = (const float*)d_in[2];   // [3,4096,1024]
    const float* Whh   = (const float*)d_in[3];   // [4,4096,1024]
    const float* bih   = (const float*)d_in[4];   // [4,4096]
    const float* bhh   = (const float*)d_in[5];   // [4,4096]
    const float* Wlast = (const float*)d_in[6];   // [1024,1024]
    const float* blast = (const float*)d_in[7];   // [1024]
    const int*   ilens = (const int*)d_in[8];     // [16]
    float* out = (float*)d_out;

    float *xg, *xb, *hT;
    __nv_bfloat16 *ah, *al, *bh, *bl;
    cudaGetSymbolAddress((void**)&xg, g_xg);
    cudaGetSymbolAddress((void**)&xb, g_x);
    cudaGetSymbolAddress((void**)&hT, g_hT);
    cudaGetSymbolAddress((void**)&ah, g_ah);
    cudaGetSymbolAddress((void**)&al, g_al);
    cudaGetSymbolAddress((void**)&bh, g_bh);
    cudaGetSymbolAddress((void**)&bl, g_bl);

    const int smem_step = CD_ * HSTRIDE * 4 + 8 * 32 * 8;  // 81920 + 2048
    cudaFuncSetAttribute(lstm_layer_kernel,
                         cudaFuncAttributeMaxDynamicSharedMemorySize, smem_step);

    const int M = B_ * T_;  // 8192

    for (int l = 0; l < LAYERS_; ++l) {
        const float* Ain = (l == 0) ? xpad : xb;
        const float* Bw  = (l == 0) ? Wih0 : (WihR + (size_t)(l - 1) * GD_ * CD_);
        const int K = (l == 0) ? IDIM_ : CD_;

        // bf16 split conversions
        {
            int nA = M * K;
            conv_split_kernel<<<(nA / 2 + 255) / 256, 256>>>(Ain, ah, al, nA, K, nullptr);
            int nB = GD_ * K;
            conv_split_kernel<<<(nB / 2 + 255) / 256, 256>>>(Bw, bh, bl, nB, K, nullptr);
        }

        dim3 grid_xg(GD_ / 128, M / 128);
        gemm_bf16x3_kernel<0><<<grid_xg, 256>>>(ah, al, bh, bl,
                                                bih + l * GD_, bhh + l * GD_,
                                                xg, M, GD_, K);

        const float* Wl = Whh + (size_t)l * GD_ * CD_;
        lstm_layer_kernel<<<NBLK_, 512, smem_step>>>(Wl, xg, xb, hT);
    }

    // projection: mask ys rows (t >= ilens[b]) during conversion, tanh epilogue
    {
        int nA = M * CD_;
        conv_split_kernel<<<(nA / 2 + 255) / 256, 256>>>(xb, ah, al, nA, CD_, ilens);
        int nB = HD_ * CD_;
        conv_split_kernel<<<(nB / 2 + 255) / 256, 256>>>(Wlast, bh, bl, nB, CD_, nullptr);
        dim3 grid_p(HD_ / 128, M / 128);
        gemm_bf16x3_kernel<1><<<grid_p, 256>>>(ah, al, bh, bl, blast, nullptr,
                                               out, M, HD_, CD_);
    }

    const long long base = (long long)B_ * T_ * HD_;  // 8388608
    if ((long long)out_size > base)
        write_tail_kernel<<<1, 32>>>(out, ilens, base, (long long)out_size);
}